// round 1
// baseline (speedup 1.0000x reference)
#include <cuda_runtime.h>
#include <cstdint>

// ---------------- model constants ----------------
#define TT     3
#define LL     3
#define EE     50000
#define NN     1000000
#define RRR    200
#define NRELC  401
#define HHH    256
#define TOPKC  1000
#define BBB    8
#define K32    32     // padded channel count (24 used: k = b*3 + l)

// ---------------- device scratch (no allocs allowed) ----------------
__device__ float g_x[EE * K32];        // entity state input to a hop
__device__ float g_s[EE * K32];        // entity state output of a hop (unnormalized)
__device__ float g_w[TT * NRELC * K32];// per-hop softmax relation weights, [t][r][k]
__device__ float g_pre[6 * 4 * BBB * 1024]; // LSTM input projections [ld][t][b][4H]
__device__ float g_h[6 * 4 * BBB * HHH];    // LSTM hidden states    [ld][t][b][H]
__device__ float g_c[6 * BBB * HHH];        // LSTM cell state       [ld][b][H]
__device__ float g_th[K32];            // per-(b,l) top-k thresholds (unnormalized)
__device__ float g_sumraw[K32];        // per-(b,l) sums of g_s (unnormalized)

__device__ __forceinline__ float sigf(float x) { return 1.0f / (1.0f + expf(-x)); }

// ---------------- LSTM: input projections ----------------
// pre[ld][t][b][j] = emb[rsel] . Wih[j,:] + bih[j] + bhh[j]
__global__ void pre_kernel(const int* __restrict__ input_r, const float* __restrict__ emb,
                           const float* __restrict__ Wih_f, const float* __restrict__ bih_f,
                           const float* __restrict__ bhh_f,
                           const float* __restrict__ Wih_b, const float* __restrict__ bih_b,
                           const float* __restrict__ bhh_b) {
    int ld = blockIdx.y;          // 0..5: l*2 + dir
    int l = ld >> 1, dir = ld & 1;
    int t = blockIdx.x >> 3, b = blockIdx.x & 7;

    const float* Wih = (dir ? Wih_b : Wih_f) + l * 1024 * HHH;
    const float* bih = (dir ? bih_b : bih_f) + l * 1024;
    const float* bhh = (dir ? bhh_b : bhh_f) + l * 1024;

    int rsel;
    if (!dir) rsel = (t < 3) ? input_r[b] : (NRELC - 1);
    else      rsel = (t == 0) ? (NRELC - 1) : input_r[b];

    __shared__ float sin_[HHH];
    if (threadIdx.x < HHH) sin_[threadIdx.x] = emb[rsel * HHH + threadIdx.x];
    __syncthreads();

    int warp = threadIdx.x >> 5, lane = threadIdx.x & 31;
    const float4* s4 = (const float4*)sin_;
    float4 h1 = s4[lane * 2], h2 = s4[lane * 2 + 1];

    for (int rr = 0; rr < 128; rr++) {
        int j = warp * 128 + rr;
        const float4* w4 = (const float4*)(Wih + j * HHH);
        float4 a = w4[lane * 2], bq = w4[lane * 2 + 1];
        float acc = a.x * h1.x + a.y * h1.y + a.z * h1.z + a.w * h1.w
                  + bq.x * h2.x + bq.y * h2.y + bq.z * h2.z + bq.w * h2.w;
        #pragma unroll
        for (int o = 16; o; o >>= 1) acc += __shfl_down_sync(0xFFFFFFFFu, acc, o);
        if (lane == 0)
            g_pre[((ld * 4 + t) * BBB + b) * 1024 + j] = acc + bih[j] + bhh[j];
    }
}

// ---------------- LSTM: one recurrent step ----------------
// grid (8, 6), block 128: tid = g*32 + kc ; kcol = bx*32+kc
__global__ void step_kernel(int step, const float* __restrict__ Whh_f,
                            const float* __restrict__ Whh_b) {
    int ld = blockIdx.y;
    int l = ld >> 1, dir = ld & 1;
    const float* Whh = (dir ? Whh_b : Whh_f) + l * 1024 * HHH;

    __shared__ float sh[BBB * HHH];     // h_prev
    __shared__ float sg[4][32][BBB];    // gate pre-activations

    int tid = threadIdx.x;
    if (step > 0) {
        const float* hp = &g_h[((ld * 4 + (step - 1)) * BBB) * HHH];
        for (int i = tid; i < BBB * HHH; i += 128) sh[i] = hp[i];
    }
    __syncthreads();

    int kc = tid & 31, g = tid >> 5;
    int kcol = blockIdx.x * 32 + kc;
    int j = g * HHH + kcol;

    float acc[BBB];
    #pragma unroll
    for (int b = 0; b < BBB; b++)
        acc[b] = g_pre[((ld * 4 + step) * BBB + b) * 1024 + j];

    if (step > 0) {
        const float4* w4 = (const float4*)(Whh + j * HHH);
        const float4* h4 = (const float4*)sh;
        for (int kk = 0; kk < HHH / 4; kk++) {
            float4 w = w4[kk];
            #pragma unroll
            for (int b = 0; b < BBB; b++) {
                float4 h = h4[b * (HHH / 4) + kk];
                acc[b] += w.x * h.x + w.y * h.y + w.z * h.z + w.w * h.w;
            }
        }
    }
    #pragma unroll
    for (int b = 0; b < BBB; b++) sg[g][kc][b] = acc[b];
    __syncthreads();

    for (int task = tid; task < 256; task += 128) {
        int b = task & 7, kc2 = task >> 3;
        int kcol2 = blockIdx.x * 32 + kc2;
        float gi = sg[0][kc2][b], gf = sg[1][kc2][b];
        float gg = sg[2][kc2][b], go = sg[3][kc2][b];
        float cp = (step > 0) ? g_c[(ld * BBB + b) * HHH + kcol2] : 0.0f;
        float c = sigf(gf) * cp + sigf(gi) * tanhf(gg);
        float h = sigf(go) * tanhf(c);
        g_c[(ld * BBB + b) * HHH + kcol2] = c;
        g_h[((ld * 4 + step) * BBB + b) * HHH + kcol2] = h;
    }
}

// ---------------- linear + softmax -> per-hop relation weights ----------------
// grid (9, 8): bx -> (t = bx/3, l = bx%3), by = b. block 128.
__global__ void wlin_kernel(const float* __restrict__ linW, const float* __restrict__ linb) {
    int t = blockIdx.x / 3, l = blockIdx.x % 3, b = blockIdx.y;
    __shared__ float rnn[2 * HHH];
    __shared__ float logit[NRELC];
    __shared__ float red[128];
    int tid = threadIdx.x;

    const float* hf = &g_h[(((l * 2 + 0) * 4 + t) * BBB + b) * HHH];
    const float* hb = &g_h[(((l * 2 + 1) * 4 + (3 - t)) * BBB + b) * HHH];
    for (int i = tid; i < HHH; i += 128) { rnn[i] = hf[i]; rnn[HHH + i] = hb[i]; }
    __syncthreads();

    const float4* r4 = (const float4*)rnn;
    for (int n = tid; n < NRELC; n += 128) {
        const float4* w4 = (const float4*)(linW + n * 2 * HHH);
        float acc = 0.0f;
        for (int kk = 0; kk < (2 * HHH) / 4; kk++) {
            float4 w = w4[kk]; float4 r = r4[kk];
            acc += w.x * r.x + w.y * r.y + w.z * r.z + w.w * r.w;
        }
        logit[n] = acc + linb[n];
    }
    __syncthreads();

    float m = -1e30f;
    for (int n = tid; n < NRELC; n += 128) m = fmaxf(m, logit[n]);
    red[tid] = m; __syncthreads();
    for (int o = 64; o; o >>= 1) { if (tid < o) red[tid] = fmaxf(red[tid], red[tid + o]); __syncthreads(); }
    m = red[0]; __syncthreads();

    float s = 0.0f;
    for (int n = tid; n < NRELC; n += 128) {
        float e = expf((logit[n] - m) / 10.0f);   // TAU = 10
        logit[n] = e; s += e;
    }
    red[tid] = s; __syncthreads();
    for (int o = 64; o; o >>= 1) { if (tid < o) red[tid] += red[tid + o]; __syncthreads(); }
    s = red[0];

    int k = b * 3 + l;
    for (int n = tid; n < NRELC; n += 128)
        g_w[(t * NRELC + n) * K32 + k] = logit[n] / s;
}

// ---------------- exact top-k threshold per (b,l): 3-pass radix select ----------------
__global__ void select_kernel() {
    int k = blockIdx.x;                 // 0..23
    __shared__ unsigned hist[2048];
    __shared__ unsigned s_sel, s_need;
    int tid = threadIdx.x;              // 512

    unsigned need = TOPKC;
    unsigned hi = 0;
    int hishift = 32;

    const int shifts[3] = {21, 10, 0};
    const int bits[3]   = {11, 11, 10};

    for (int p = 0; p < 3; p++) {
        int sh = shifts[p], nb = bits[p];
        unsigned nbins = 1u << nb;
        for (unsigned i = tid; i < nbins; i += 512) hist[i] = 0;
        __syncthreads();
        for (int e = tid; e < EE; e += 512) {
            unsigned u = __float_as_uint(g_s[e * K32 + k]);
            if (u == 0x80000000u) u = 0;   // fold -0 to +0
            bool ok = (p == 0) || ((u >> hishift) == hi);
            if (ok) atomicAdd(&hist[(u >> sh) & (nbins - 1)], 1u);
        }
        __syncthreads();
        if (tid == 0) {
            unsigned cum = 0, sel = 0, nn = need;
            for (int bkt = (int)nbins - 1; bkt >= 0; bkt--) {
                cum += hist[bkt];
                if (cum >= nn) { sel = (unsigned)bkt; nn = nn - (cum - hist[bkt]); break; }
            }
            s_sel = sel; s_need = nn;
        }
        __syncthreads();
        need = s_need;
        hi = (hi << nb) | s_sel;
        hishift = sh;
        __syncthreads();
    }
    if (tid == 0) g_th[k] = __uint_as_float(hi);
}

// ---------------- x builders ----------------
__global__ void buildx0_kernel(const int* __restrict__ input_x) {
    __shared__ int xs[BBB];
    if (threadIdx.x < BBB) xs[threadIdx.x] = input_x[threadIdx.x];
    __syncthreads();
    int stride = gridDim.x * blockDim.x;
    for (int i = blockIdx.x * blockDim.x + threadIdx.x; i < EE * K32; i += stride) {
        int k = i & 31, e = i >> 5;
        float v = 0.0f;
        if (k < 24 && xs[k / 3] == e) v = 1.0f;
        g_x[i] = v;
    }
}

__global__ void buildx_kernel() {
    int stride = gridDim.x * blockDim.x;
    for (int i = blockIdx.x * blockDim.x + threadIdx.x; i < EE * K32; i += stride) {
        int k = i & 31;
        float v = g_s[i];
        float th = g_th[k];
        float denom = fmaxf(g_sumraw[k], 1e-7f);
        g_x[i] = (v >= th) ? (v / denom) : 0.0f;
    }
}

// ---------------- init st with identity term; zero sums ----------------
__global__ void init_st_kernel(int t) {
    int gtid = blockIdx.x * blockDim.x + threadIdx.x;
    if (gtid < K32) g_sumraw[gtid] = 0.0f;
    const float* wid = &g_w[(t * NRELC + (NRELC - 1)) * K32];
    int stride = gridDim.x * blockDim.x;
    for (int i = gtid; i < EE * K32; i += stride) {
        int k = i & 31;
        g_s[i] = wid[k] * g_x[i];
    }
}

// ---------------- propagate: warp per triple, per-lane zero-skip atomics ----------------
__global__ void prop_kernel(int t, const int* __restrict__ heads, const int* __restrict__ tails,
                            const int* __restrict__ tails2, const int* __restrict__ rels) {
    int lane = threadIdx.x & 31;
    int warp_id = (blockIdx.x * blockDim.x + threadIdx.x) >> 5;
    int nwarps = (gridDim.x * blockDim.x) >> 5;
    const float* wt = &g_w[t * NRELC * K32];

    for (int i = warp_id; i < NN; i += nwarps) {
        int h  = heads[i];
        int tl = tails[i];
        int t2 = tails2[i];
        int r  = rels[i];

        float m = g_x[h * K32 + lane] * wt[r * K32 + lane];
        if (m != 0.0f) atomicAdd(&g_s[tl * K32 + lane], m);

        float m2 = g_x[t2 * K32 + lane] * wt[(r + RRR) * K32 + lane];
        if (m2 != 0.0f) atomicAdd(&g_s[h * K32 + lane], m2);
    }
}

// ---------------- per-(b,l) sums of g_s ----------------
__global__ void sums_kernel() {
    int tid = blockIdx.x * blockDim.x + threadIdx.x;
    int k = threadIdx.x & 31;                 // fixed per thread: stride multiple of 32
    float acc = 0.0f;
    int stride = gridDim.x * blockDim.x;
    for (int i = tid; i < EE * K32; i += stride) acc += g_s[i];
    __shared__ float sm[8][32];
    sm[threadIdx.x >> 5][k] = acc;
    __syncthreads();
    if (threadIdx.x < 32) {
        float a = 0.0f;
        #pragma unroll
        for (int w = 0; w < 8; w++) a += sm[w][threadIdx.x];
        if (a != 0.0f) atomicAdd(&g_sumraw[threadIdx.x], a);
    }
}

// ---------------- final output: out[b,e] = sum_l s[e][b*3+l] / denom ----------------
__global__ void out_kernel(float* __restrict__ out) {
    int stride = gridDim.x * blockDim.x;
    for (int idx = blockIdx.x * blockDim.x + threadIdx.x; idx < BBB * EE; idx += stride) {
        int b = idx / EE, e = idx - b * EE;
        float acc = 0.0f;
        #pragma unroll
        for (int l = 0; l < LL; l++) {
            int k = b * 3 + l;
            acc += g_s[e * K32 + k] / fmaxf(g_sumraw[k], 1e-7f);
        }
        out[idx] = acc;
    }
}

// ---------------- launch ----------------
extern "C" void kernel_launch(void* const* d_in, const int* in_sizes, int n_in,
                              void* d_out, int out_size) {
    const int*   input_x  = (const int*)d_in[0];
    const int*   input_r  = (const int*)d_in[1];
    const int*   e2triple = (const int*)d_in[2];   // [3,N]: row0 heads, row2 tails2
    const int*   triple2e = (const int*)d_in[3];   // [2,N]: row1 tails
    const int*   r2triple = (const int*)d_in[4];   // [1,N]
    const float* emb      = (const float*)d_in[5];
    const float* Wih_f    = (const float*)d_in[6];
    const float* Whh_f    = (const float*)d_in[7];
    const float* bih_f    = (const float*)d_in[8];
    const float* bhh_f    = (const float*)d_in[9];
    const float* Wih_b    = (const float*)d_in[10];
    const float* Whh_b    = (const float*)d_in[11];
    const float* bih_b    = (const float*)d_in[12];
    const float* bhh_b    = (const float*)d_in[13];
    const float* linW     = (const float*)d_in[14];
    const float* linb     = (const float*)d_in[15];

    const int* heads  = e2triple;            // e2triple[0]
    const int* tails2 = e2triple + 2 * NN;   // e2triple[2]
    const int* tails  = triple2e + NN;       // triple2e[1]
    const int* rels   = r2triple;            // r2triple[0]

    // LSTM part
    pre_kernel<<<dim3(32, 6), 256>>>(input_r, emb, Wih_f, bih_f, bhh_f, Wih_b, bih_b, bhh_b);
    for (int s = 0; s < 4; s++)
        step_kernel<<<dim3(8, 6), 128>>>(s, Whh_f, Whh_b);
    wlin_kernel<<<dim3(9, 8), 128>>>(linW, linb);

    // Hops
    for (int t = 0; t < TT; t++) {
        if (t == 0) {
            buildx0_kernel<<<2048, 256>>>(input_x);
        } else {
            select_kernel<<<24, 512>>>();
            buildx_kernel<<<2048, 256>>>();
        }
        init_st_kernel<<<2048, 256>>>(t);
        prop_kernel<<<2048, 256>>>(t, heads, tails, tails2, rels);
        sums_kernel<<<512, 256>>>();
    }

    out_kernel<<<1024, 256>>>((float*)d_out);
}

// round 2
// speedup vs baseline: 1.1346x; 1.1346x over previous
#include <cuda_runtime.h>
#include <cstdint>

// ---------------- model constants ----------------
#define TT     3
#define LL     3
#define EE     50000
#define NN     1000000
#define RRR    200
#define NRELC  401
#define HHH    256
#define TOPKC  1000
#define BBB    8
#define K32    32     // padded channel count (24 used: k = b*3 + l)

// ---------------- device scratch ----------------
__device__ float g_x[EE * K32];              // entity state input to a hop
__device__ float g_s[EE * K32];              // entity state output (unnormalized)
__device__ unsigned char g_actb[EE];         // per-entity "row has any nonzero x" flag
__device__ float g_w[TT * NRELC * K32];      // per-hop softmax relation weights [t][r][k]
__device__ float g_pre[6 * 4 * BBB * 1024];  // LSTM input projections [ld][t][b][4H]
__device__ float g_h[6 * 4 * BBB * HHH];     // LSTM hidden states    [ld][t][b][H]
__device__ float g_c[6 * BBB * HHH];         // LSTM cell state       [ld][b][H]
__device__ float g_th[K32];                  // per-(b,l) top-k thresholds (unnormalized)
__device__ float g_sumraw[K32];              // per-(b,l) sums of g_s (unnormalized)
__device__ float g_part[256][K32];           // partial sums

__device__ __forceinline__ float sigf(float x) { return 1.0f / (1.0f + expf(-x)); }

// ---------------- LSTM: input projections ----------------
// Only 9 distinct input vectors exist: emb[input_r[b]] (b=0..7) and emb[400].
// grid (32, 6), block 256: 32 rows/block, 8 threads/row.
__global__ void pre_kernel(const int* __restrict__ input_r, const float* __restrict__ emb,
                           const float* __restrict__ Wih_f, const float* __restrict__ bih_f,
                           const float* __restrict__ bhh_f,
                           const float* __restrict__ Wih_b, const float* __restrict__ bih_b,
                           const float* __restrict__ bhh_b) {
    int ld = blockIdx.y, l = ld >> 1, dir = ld & 1;
    const float* Wih = (dir ? Wih_b : Wih_f) + l * 1024 * HHH;
    const float* bih = (dir ? bih_b : bih_f) + l * 1024;
    const float* bhh = (dir ? bhh_b : bhh_f) + l * 1024;

    __shared__ float sv[9][HHH];
    __shared__ int sr[8];
    int tid = threadIdx.x;
    if (tid < 8) sr[tid] = input_r[tid];
    __syncthreads();
    for (int i = tid; i < 9 * HHH; i += 256) {
        int v = i >> 8, c = i & 255;
        int rs = (v < 8) ? sr[v] : (NRELC - 1);
        sv[v][c] = emb[rs * HHH + c];
    }
    __syncthreads();

    int row = tid >> 3, seg = tid & 7;
    int j = blockIdx.x * 32 + row;
    const float4* w4 = (const float4*)(Wih + j * HHH + seg * 32);
    float4 w[8];
    #pragma unroll
    for (int q = 0; q < 8; q++) w[q] = w4[q];

    float acc[9];
    #pragma unroll
    for (int v = 0; v < 9; v++) {
        const float4* s4 = (const float4*)(&sv[v][seg * 32]);
        float a = 0.0f;
        #pragma unroll
        for (int q = 0; q < 8; q++) {
            float4 s = s4[q];
            a += w[q].x * s.x + w[q].y * s.y + w[q].z * s.z + w[q].w * s.w;
        }
        acc[v] = a;
    }
    #pragma unroll
    for (int v = 0; v < 9; v++)
        #pragma unroll
        for (int o = 4; o; o >>= 1) acc[v] += __shfl_down_sync(0xFFFFFFFFu, acc[v], o, 8);

    if (seg == 0) {
        float bb = bih[j] + bhh[j];
        if (!dir) {
            #pragma unroll
            for (int t = 0; t < 4; t++)
                #pragma unroll
                for (int b = 0; b < 8; b++)
                    g_pre[((ld * 4 + t) * BBB + b) * 1024 + j] = acc[(t < 3) ? b : 8] + bb;
        } else {
            #pragma unroll
            for (int t = 0; t < 4; t++)
                #pragma unroll
                for (int b = 0; b < 8; b++)
                    g_pre[((ld * 4 + t) * BBB + b) * 1024 + j] = acc[(t == 0) ? 8 : b] + bb;
        }
    }
}

// ---------------- LSTM: one recurrent step ----------------
// grid (32, 6), block 256: each block = 8 kcols x 4 gates = 32 rows, 8 threads/row.
__global__ void step_kernel(int step, const float* __restrict__ Whh_f,
                            const float* __restrict__ Whh_b) {
    int ld = blockIdx.y, l = ld >> 1, dir = ld & 1;
    const float* Whh = (dir ? Whh_b : Whh_f) + l * 1024 * HHH;

    __shared__ float sh[BBB * HHH];
    __shared__ float sg[32][BBB];
    int tid = threadIdx.x;
    if (step > 0) {
        const float* hp = &g_h[((ld * 4 + (step - 1)) * BBB) * HHH];
        for (int i = tid; i < BBB * HHH; i += 256) sh[i] = hp[i];
    }
    __syncthreads();

    int row = tid >> 3, seg = tid & 7;
    int gate = row >> 3, kc = row & 7;
    int kcol = blockIdx.x * 8 + kc;
    int j = gate * HHH + kcol;

    float acc[BBB];
    #pragma unroll
    for (int b = 0; b < BBB; b++) acc[b] = 0.0f;

    if (step > 0) {
        const float4* w4 = (const float4*)(Whh + j * HHH + seg * 32);
        float4 w[8];
        #pragma unroll
        for (int q = 0; q < 8; q++) w[q] = w4[q];
        #pragma unroll
        for (int b = 0; b < BBB; b++) {
            const float4* h4 = (const float4*)(&sh[b * HHH + seg * 32]);
            float a = 0.0f;
            #pragma unroll
            for (int q = 0; q < 8; q++) {
                float4 h = h4[q];
                a += w[q].x * h.x + w[q].y * h.y + w[q].z * h.z + w[q].w * h.w;
            }
            acc[b] = a;
        }
    }
    #pragma unroll
    for (int b = 0; b < BBB; b++)
        #pragma unroll
        for (int o = 4; o; o >>= 1) acc[b] += __shfl_down_sync(0xFFFFFFFFu, acc[b], o, 8);

    if (seg == 0) {
        #pragma unroll
        for (int b = 0; b < BBB; b++)
            sg[row][b] = acc[b] + g_pre[((ld * 4 + step) * BBB + b) * 1024 + j];
    }
    __syncthreads();

    if (tid < 64) {
        int b = tid & 7, kc2 = tid >> 3;
        int kcol2 = blockIdx.x * 8 + kc2;
        float gi = sg[0 * 8 + kc2][b], gf = sg[1 * 8 + kc2][b];
        float gg = sg[2 * 8 + kc2][b], go = sg[3 * 8 + kc2][b];
        float cp = (step > 0) ? g_c[(ld * BBB + b) * HHH + kcol2] : 0.0f;
        float c = sigf(gf) * cp + sigf(gi) * tanhf(gg);
        float h = sigf(go) * tanhf(c);
        g_c[(ld * BBB + b) * HHH + kcol2] = c;
        g_h[((ld * 4 + step) * BBB + b) * HHH + kcol2] = h;
    }
}

// ---------------- linear + softmax -> relation weights ----------------
__global__ void wlin_kernel(const float* __restrict__ linW, const float* __restrict__ linb) {
    int t = blockIdx.x / 3, l = blockIdx.x % 3, b = blockIdx.y;
    __shared__ float rnn[2 * HHH];
    __shared__ float logit[NRELC];
    __shared__ float red[128];
    int tid = threadIdx.x;

    const float* hf = &g_h[(((l * 2 + 0) * 4 + t) * BBB + b) * HHH];
    const float* hb = &g_h[(((l * 2 + 1) * 4 + (3 - t)) * BBB + b) * HHH];
    for (int i = tid; i < HHH; i += 128) { rnn[i] = hf[i]; rnn[HHH + i] = hb[i]; }
    __syncthreads();

    const float4* r4 = (const float4*)rnn;
    for (int n = tid; n < NRELC; n += 128) {
        const float4* w4 = (const float4*)(linW + n * 2 * HHH);
        float acc = 0.0f;
        for (int kk = 0; kk < (2 * HHH) / 4; kk++) {
            float4 w = w4[kk]; float4 r = r4[kk];
            acc += w.x * r.x + w.y * r.y + w.z * r.z + w.w * r.w;
        }
        logit[n] = acc + linb[n];
    }
    __syncthreads();

    float m = -1e30f;
    for (int n = tid; n < NRELC; n += 128) m = fmaxf(m, logit[n]);
    red[tid] = m; __syncthreads();
    for (int o = 64; o; o >>= 1) { if (tid < o) red[tid] = fmaxf(red[tid], red[tid + o]); __syncthreads(); }
    m = red[0]; __syncthreads();

    float s = 0.0f;
    for (int n = tid; n < NRELC; n += 128) {
        float e = expf((logit[n] - m) / 10.0f);
        logit[n] = e; s += e;
    }
    red[tid] = s; __syncthreads();
    for (int o = 64; o; o >>= 1) { if (tid < o) red[tid] += red[tid + o]; __syncthreads(); }
    s = red[0];

    int k = b * 3 + l;
    for (int n = tid; n < NRELC; n += 128)
        g_w[(t * NRELC + n) * K32 + k] = logit[n] / s;
}

// ---------------- exact top-k threshold: 3-pass radix select ----------------
__global__ void select_kernel() {
    int k = blockIdx.x;                 // 0..23
    __shared__ unsigned hist[2048];
    __shared__ unsigned s_sel, s_need;
    int tid = threadIdx.x;              // 512

    unsigned need = TOPKC;
    unsigned hi = 0;
    int hishift = 32;
    const int shifts[3] = {21, 10, 0};
    const int bits[3]   = {11, 11, 10};

    for (int p = 0; p < 3; p++) {
        int sh = shifts[p], nb = bits[p];
        unsigned nbins = 1u << nb;
        for (unsigned i = tid; i < nbins; i += 512) hist[i] = 0;
        __syncthreads();
        for (int e = tid; e < EE; e += 512) {
            unsigned u = __float_as_uint(g_s[e * K32 + k]);
            if (u == 0x80000000u) u = 0;
            bool ok = (p == 0) || ((u >> hishift) == hi);
            if (ok) atomicAdd(&hist[(u >> sh) & (nbins - 1)], 1u);
        }
        __syncthreads();
        if (tid == 0) {
            unsigned cum = 0, sel = 0, nn = need;
            for (int bkt = (int)nbins - 1; bkt >= 0; bkt--) {
                cum += hist[bkt];
                if (cum >= nn) { sel = (unsigned)bkt; nn = nn - (cum - hist[bkt]); break; }
            }
            s_sel = sel; s_need = nn;
        }
        __syncthreads();
        need = s_need;
        hi = (hi << nb) | s_sel;
        hishift = sh;
        __syncthreads();
    }
    if (tid == 0) g_th[k] = __uint_as_float(hi);
}

// ---------------- x builders (fused with identity-init of g_s + activity mask) ----------------
__global__ void buildx0_kernel(const int* __restrict__ input_x) {
    __shared__ int xs[BBB];
    if (threadIdx.x < BBB) xs[threadIdx.x] = input_x[threadIdx.x];
    __syncthreads();
    int lane = threadIdx.x & 31;
    int warp = (blockIdx.x * blockDim.x + threadIdx.x) >> 5;
    int nw = (gridDim.x * blockDim.x) >> 5;
    float wid = g_w[(0 * NRELC + (NRELC - 1)) * K32 + lane];
    int bsel = (lane < 24) ? (lane / 3) : 0;
    for (int e = warp; e < EE; e += nw) {
        float x = (lane < 24 && xs[bsel] == e) ? 1.0f : 0.0f;
        g_x[e * K32 + lane] = x;
        g_s[e * K32 + lane] = wid * x;
        unsigned nz = __ballot_sync(0xFFFFFFFFu, x != 0.0f);
        if (lane == 0) g_actb[e] = nz ? 1 : 0;
    }
}

__global__ void buildx_kernel(int t) {
    int lane = threadIdx.x & 31;
    int warp = (blockIdx.x * blockDim.x + threadIdx.x) >> 5;
    int nw = (gridDim.x * blockDim.x) >> 5;
    float wid = g_w[(t * NRELC + (NRELC - 1)) * K32 + lane];
    float th = g_th[lane];
    float denom = fmaxf(g_sumraw[lane], 1e-7f);
    for (int e = warp; e < EE; e += nw) {
        float v = g_s[e * K32 + lane];
        float x = (v >= th) ? (v / denom) : 0.0f;
        g_x[e * K32 + lane] = x;
        g_s[e * K32 + lane] = wid * x;
        unsigned nz = __ballot_sync(0xFFFFFFFFu, x != 0.0f);
        if (lane == 0) g_actb[e] = nz ? 1 : 0;
    }
}

// ---------------- propagate: 32 triples per warp, activity-masked ----------------
__global__ void prop_kernel(int t, const int* __restrict__ heads, const int* __restrict__ tails,
                            const int* __restrict__ tails2, const int* __restrict__ rels) {
    int lane = threadIdx.x & 31;
    int warp = (blockIdx.x * blockDim.x + threadIdx.x) >> 5;
    int nw = (gridDim.x * blockDim.x) >> 5;
    const float* wt = &g_w[t * NRELC * K32];

    for (int base = warp * 32; base < NN; base += nw * 32) {
        int i = base + lane;                // NN % 32 == 0, always in range
        int h  = heads[i];
        int t2 = tails2[i];
        unsigned mf = __ballot_sync(0xFFFFFFFFu, g_actb[h] != 0);
        unsigned mb = __ballot_sync(0xFFFFFFFFu, g_actb[t2] != 0);
        if (!(mf | mb)) continue;
        int r = rels[i];
        int tl = mf ? tails[i] : 0;

        unsigned m = mf;
        while (m) {
            int j = __ffs(m) - 1; m &= m - 1;
            int hj  = __shfl_sync(0xFFFFFFFFu, h,  j);
            int tlj = __shfl_sync(0xFFFFFFFFu, tl, j);
            int rj  = __shfl_sync(0xFFFFFFFFu, r,  j);
            float mm = g_x[hj * K32 + lane] * wt[rj * K32 + lane];
            if (mm != 0.0f) atomicAdd(&g_s[tlj * K32 + lane], mm);
        }
        m = mb;
        while (m) {
            int j = __ffs(m) - 1; m &= m - 1;
            int t2j = __shfl_sync(0xFFFFFFFFu, t2, j);
            int hj  = __shfl_sync(0xFFFFFFFFu, h,  j);
            int rj  = __shfl_sync(0xFFFFFFFFu, r,  j);
            float mm = g_x[t2j * K32 + lane] * wt[(rj + RRR) * K32 + lane];
            if (mm != 0.0f) atomicAdd(&g_s[hj * K32 + lane], mm);
        }
    }
}

// ---------------- per-(b,l) sums: two-stage, no global atomics ----------------
__global__ void sums1_kernel() {
    int tid = blockIdx.x * blockDim.x + threadIdx.x;
    int lane = threadIdx.x & 31;
    float a = 0.0f;
    int stride = gridDim.x * blockDim.x;
    for (int i = tid; i < EE * K32; i += stride) a += g_s[i];
    __shared__ float sm[8][32];
    sm[threadIdx.x >> 5][lane] = a;
    __syncthreads();
    if (threadIdx.x < 32) {
        float s = 0.0f;
        #pragma unroll
        for (int w = 0; w < 8; w++) s += sm[w][threadIdx.x];
        g_part[blockIdx.x][threadIdx.x] = s;
    }
}

__global__ void sums2_kernel() {
    int k = threadIdx.x;   // 32 threads
    float s = 0.0f;
    for (int i = 0; i < 256; i++) s += g_part[i][k];
    g_sumraw[k] = s;
}

// ---------------- final output ----------------
__global__ void out_kernel(float* __restrict__ out) {
    int stride = gridDim.x * blockDim.x;
    for (int idx = blockIdx.x * blockDim.x + threadIdx.x; idx < BBB * EE; idx += stride) {
        int b = idx / EE, e = idx - b * EE;
        float acc = 0.0f;
        #pragma unroll
        for (int l = 0; l < LL; l++) {
            int k = b * 3 + l;
            acc += g_s[e * K32 + k] / fmaxf(g_sumraw[k], 1e-7f);
        }
        out[idx] = acc;
    }
}

// ---------------- launch ----------------
extern "C" void kernel_launch(void* const* d_in, const int* in_sizes, int n_in,
                              void* d_out, int out_size) {
    const int*   input_x  = (const int*)d_in[0];
    const int*   input_r  = (const int*)d_in[1];
    const int*   e2triple = (const int*)d_in[2];
    const int*   triple2e = (const int*)d_in[3];
    const int*   r2triple = (const int*)d_in[4];
    const float* emb      = (const float*)d_in[5];
    const float* Wih_f    = (const float*)d_in[6];
    const float* Whh_f    = (const float*)d_in[7];
    const float* bih_f    = (const float*)d_in[8];
    const float* bhh_f    = (const float*)d_in[9];
    const float* Wih_b    = (const float*)d_in[10];
    const float* Whh_b    = (const float*)d_in[11];
    const float* bih_b    = (const float*)d_in[12];
    const float* bhh_b    = (const float*)d_in[13];
    const float* linW     = (const float*)d_in[14];
    const float* linb     = (const float*)d_in[15];

    const int* heads  = e2triple;
    const int* tails2 = e2triple + 2 * NN;
    const int* tails  = triple2e + NN;
    const int* rels   = r2triple;

    // LSTM part
    pre_kernel<<<dim3(32, 6), 256>>>(input_r, emb, Wih_f, bih_f, bhh_f, Wih_b, bih_b, bhh_b);
    for (int s = 0; s < 4; s++)
        step_kernel<<<dim3(32, 6), 256>>>(s, Whh_f, Whh_b);
    wlin_kernel<<<dim3(9, 8), 128>>>(linW, linb);

    // Hops
    for (int t = 0; t < TT; t++) {
        if (t == 0) {
            buildx0_kernel<<<256, 256>>>(input_x);
        } else {
            select_kernel<<<24, 512>>>();
            buildx_kernel<<<256, 256>>>(t);
        }
        prop_kernel<<<1024, 256>>>(t, heads, tails, tails2, rels);
        sums1_kernel<<<256, 256>>>();
        sums2_kernel<<<1, 32>>>();
    }

    out_kernel<<<512, 256>>>((float*)d_out);
}

// round 3
// speedup vs baseline: 2.6760x; 2.3586x over previous
#include <cuda_runtime.h>
#include <cstdint>

// ---------------- model constants ----------------
#define TT     3
#define LL     3
#define EE     50000
#define NN     1000000
#define RRR    200
#define NRELC  401
#define HHH    256
#define TOPKC  1000
#define BBB    8
#define K32    32

// ---------------- device scratch ----------------
__device__ float g_x[EE * K32];
__device__ float g_s[EE * K32];
__device__ unsigned char g_actb[EE];
__device__ float g_w[TT * NRELC * K32];
__device__ float g_pre[6 * 4 * BBB * 1024];
__device__ float g_h[6 * 4 * BBB * HHH];
__device__ float g_c[6 * BBB * HHH];
__device__ float g_th[K32];
__device__ float g_sumraw[K32];
__device__ int   g_cnt[2];
__device__ int   g_list_f[NN];
__device__ int   g_list_b[NN];
__device__ unsigned g_hist8[24 * 256];
__device__ unsigned g_hi[24];
__device__ unsigned g_need[24];

__device__ __forceinline__ float sigf(float x) { return 1.0f / (1.0f + expf(-x)); }
__device__ __forceinline__ float dot4(float4 a, float4 b) {
    return a.x * b.x + a.y * b.y + a.z * b.z + a.w * b.w;
}

// ---------------- LSTM: input projections (warp per row) ----------------
__global__ void pre_kernel(const int* __restrict__ input_r, const float* __restrict__ emb,
                           const float* __restrict__ Wih_f, const float* __restrict__ bih_f,
                           const float* __restrict__ bhh_f,
                           const float* __restrict__ Wih_b, const float* __restrict__ bih_b,
                           const float* __restrict__ bhh_b) {
    int ld = blockIdx.y, l = ld >> 1, dir = ld & 1;
    const float* Wih = (dir ? Wih_b : Wih_f) + l * 1024 * HHH;
    const float* bih = (dir ? bih_b : bih_f) + l * 1024;
    const float* bhh = (dir ? bhh_b : bhh_f) + l * 1024;

    __shared__ float sv[9][HHH];
    __shared__ int sr[8];
    int tid = threadIdx.x;
    if (tid < 8) sr[tid] = input_r[tid];
    __syncthreads();
    for (int i = tid; i < 9 * HHH; i += 256) {
        int v = i >> 8, c = i & 255;
        int rs = (v < 8) ? sr[v] : (NRELC - 1);
        sv[v][c] = emb[rs * HHH + c];
    }
    __syncthreads();

    int warp = tid >> 5, lane = tid & 31;
    int j = blockIdx.x * 8 + warp;                   // 0..1023
    const float4* w4 = (const float4*)(Wih + j * HHH);
    float4 w0 = w4[lane], w1 = w4[32 + lane];

    float acc[9];
    #pragma unroll
    for (int v = 0; v < 9; v++) {
        const float4* s4 = (const float4*)sv[v];
        acc[v] = dot4(w0, s4[lane]) + dot4(w1, s4[32 + lane]);
    }
    #pragma unroll
    for (int v = 0; v < 9; v++)
        #pragma unroll
        for (int o = 16; o; o >>= 1) acc[v] += __shfl_down_sync(0xFFFFFFFFu, acc[v], o);

    if (lane == 0) {
        float bb = bih[j] + bhh[j];
        #pragma unroll
        for (int t = 0; t < 4; t++)
            #pragma unroll
            for (int b = 0; b < 8; b++) {
                int v = dir ? ((t == 0) ? 8 : b) : ((t < 3) ? b : 8);
                g_pre[((ld * 4 + t) * BBB + b) * 1024 + j] = acc[v] + bb;
            }
    }
}

// ---------------- LSTM: one step (warp per row; block = 2 kcols x 4 gates) ----------------
__global__ void step_kernel(int step, const float* __restrict__ Whh_f,
                            const float* __restrict__ Whh_b) {
    int ld = blockIdx.y, l = ld >> 1, dir = ld & 1;
    const float* Whh = (dir ? Whh_b : Whh_f) + l * 1024 * HHH;

    __shared__ float sh[BBB * HHH];
    __shared__ float sg[4][2][BBB];
    int tid = threadIdx.x;
    if (step > 0) {
        const float* hp = &g_h[((ld * 4 + (step - 1)) * BBB) * HHH];
        for (int i = tid; i < BBB * HHH; i += 256) sh[i] = hp[i];
    }
    __syncthreads();

    int warp = tid >> 5, lane = tid & 31;
    int gate = warp >> 1, kc = warp & 1;
    int kcol = blockIdx.x * 2 + kc;
    int j = gate * HHH + kcol;

    float acc[BBB];
    #pragma unroll
    for (int b = 0; b < BBB; b++) acc[b] = 0.0f;

    if (step > 0) {
        const float4* w4 = (const float4*)(Whh + j * HHH);
        float4 w0 = w4[lane], w1 = w4[32 + lane];
        #pragma unroll
        for (int b = 0; b < BBB; b++) {
            const float4* h4 = (const float4*)(&sh[b * HHH]);
            acc[b] = dot4(w0, h4[lane]) + dot4(w1, h4[32 + lane]);
        }
        #pragma unroll
        for (int b = 0; b < BBB; b++)
            #pragma unroll
            for (int o = 16; o; o >>= 1) acc[b] += __shfl_down_sync(0xFFFFFFFFu, acc[b], o);
    }

    if (lane == 0) {
        #pragma unroll
        for (int b = 0; b < BBB; b++)
            sg[gate][kc][b] = acc[b] + g_pre[((ld * 4 + step) * BBB + b) * 1024 + j];
    }
    __syncthreads();

    if (tid < 16) {
        int b = tid & 7, kc2 = tid >> 3;
        int kcol2 = blockIdx.x * 2 + kc2;
        float gi = sg[0][kc2][b], gf = sg[1][kc2][b];
        float gg = sg[2][kc2][b], go = sg[3][kc2][b];
        float cp = (step > 0) ? g_c[(ld * BBB + b) * HHH + kcol2] : 0.0f;
        float c = sigf(gf) * cp + sigf(gi) * tanhf(gg);
        float h = sigf(go) * tanhf(c);
        g_c[(ld * BBB + b) * HHH + kcol2] = c;
        g_h[((ld * 4 + step) * BBB + b) * HHH + kcol2] = h;
    }
}

// ---------------- linear + softmax -> relation weights ----------------
__global__ void wlin_kernel(const float* __restrict__ linW, const float* __restrict__ linb) {
    int t = blockIdx.x / 3, l = blockIdx.x % 3, b = blockIdx.y;
    __shared__ float rnn[2 * HHH];
    __shared__ float logit[NRELC];
    __shared__ float red[128];
    int tid = threadIdx.x;

    const float* hf = &g_h[(((l * 2 + 0) * 4 + t) * BBB + b) * HHH];
    const float* hb = &g_h[(((l * 2 + 1) * 4 + (3 - t)) * BBB + b) * HHH];
    for (int i = tid; i < HHH; i += 128) { rnn[i] = hf[i]; rnn[HHH + i] = hb[i]; }
    __syncthreads();

    const float4* r4 = (const float4*)rnn;
    for (int n = tid; n < NRELC; n += 128) {
        const float4* w4 = (const float4*)(linW + n * 2 * HHH);
        float acc = 0.0f;
        for (int kk = 0; kk < (2 * HHH) / 4; kk++) acc += dot4(w4[kk], r4[kk]);
        logit[n] = acc + linb[n];
    }
    __syncthreads();

    float m = -1e30f;
    for (int n = tid; n < NRELC; n += 128) m = fmaxf(m, logit[n]);
    red[tid] = m; __syncthreads();
    for (int o = 64; o; o >>= 1) { if (tid < o) red[tid] = fmaxf(red[tid], red[tid + o]); __syncthreads(); }
    m = red[0]; __syncthreads();

    float s = 0.0f;
    for (int n = tid; n < NRELC; n += 128) {
        float e = expf((logit[n] - m) / 10.0f);
        logit[n] = e; s += e;
    }
    red[tid] = s; __syncthreads();
    for (int o = 64; o; o >>= 1) { if (tid < o) red[tid] += red[tid + o]; __syncthreads(); }
    s = red[0];

    int k = b * 3 + l;
    for (int n = tid; n < NRELC; n += 128)
        g_w[(t * NRELC + n) * K32 + k] = logit[n] / s;
}

// ---------------- select: 4x8-bit radix, coalesced all-k histogram ----------------
__global__ void sel_hist_kernel(int p) {
    // grid 128, block 256. Each block: 391-entity slab, all 24 channels.
    __shared__ unsigned hist[24][257];
    int tid = threadIdx.x;
    for (int i = tid; i < 24 * 257; i += 256) ((unsigned*)hist)[i] = 0;
    __syncthreads();

    int lane = tid & 31;
    int sh = 24 - 8 * p;
    unsigned hi = 0;
    if (p > 0 && lane < 24) hi = g_hi[lane];
    int chk = 32 - 8 * p;

    int base = blockIdx.x * 391;
    int lim = min(base + 391, EE);
    for (int e = base + (tid >> 5); e < lim; e += 8) {
        unsigned u = __float_as_uint(g_s[e * K32 + lane]);
        if (u == 0x80000000u) u = 0;
        bool ok = (lane < 24);
        if (p > 0) ok = ok && ((u >> chk) == hi);
        if (ok) atomicAdd(&hist[lane][(u >> sh) & 255], 1u);
    }
    __syncthreads();
    for (int i = tid; i < 24 * 256; i += 256) {
        unsigned v = hist[i >> 8][i & 255];
        if (v) atomicAdd(&g_hist8[i], v);
    }
}

__global__ void sel_pick_kernel(int p) {
    // grid 24, block 256
    int k = blockIdx.x, tid = threadIdx.x;
    __shared__ unsigned h[256], scan[256];
    unsigned v = g_hist8[k * 256 + tid];
    h[tid] = v; scan[tid] = v;
    __syncthreads();
    // suffix inclusive sum: scan[t] = sum_{b >= t} h[b]
    for (int o = 1; o < 256; o <<= 1) {
        unsigned add = (tid + o < 256) ? scan[tid + o] : 0u;
        __syncthreads();
        scan[tid] += add;
        __syncthreads();
    }
    unsigned need = (p == 0) ? TOPKC : g_need[k];
    unsigned cumIncl = scan[tid];
    unsigned cumAbove = cumIncl - h[tid];
    if (cumIncl >= need && cumAbove < need) {
        g_need[k] = need - cumAbove;
        unsigned nhi = (p == 0) ? (unsigned)tid : ((g_hi[k] << 8) | (unsigned)tid);
        g_hi[k] = nhi;
        if (p == 3) g_th[k] = __uint_as_float(nhi);
    }
    g_hist8[k * 256 + tid] = 0;
}

// ---------------- x builders (fused identity-init + activity mask) ----------------
__global__ void buildx0_kernel(const int* __restrict__ input_x) {
    __shared__ int xs[BBB];
    if (threadIdx.x < BBB) xs[threadIdx.x] = input_x[threadIdx.x];
    __syncthreads();
    int gtid = blockIdx.x * blockDim.x + threadIdx.x;
    if (gtid < 2) g_cnt[gtid] = 0;
    if (gtid < 24 * 256) g_hist8[gtid] = 0;
    int lane = threadIdx.x & 31;
    int warp = gtid >> 5;
    int nw = (gridDim.x * blockDim.x) >> 5;
    float wid = g_w[(0 * NRELC + (NRELC - 1)) * K32 + lane];
    int bsel = (lane < 24) ? (lane / 3) : 0;
    for (int e = warp; e < EE; e += nw) {
        float x = (lane < 24 && xs[bsel] == e) ? 1.0f : 0.0f;
        g_x[e * K32 + lane] = x;
        g_s[e * K32 + lane] = wid * x;
        unsigned nz = __ballot_sync(0xFFFFFFFFu, x != 0.0f);
        if (lane == 0) g_actb[e] = nz ? 1 : 0;
    }
}

__global__ void buildx_kernel(int t) {
    int gtid = blockIdx.x * blockDim.x + threadIdx.x;
    if (gtid < 2) g_cnt[gtid] = 0;
    int lane = threadIdx.x & 31;
    int warp = gtid >> 5;
    int nw = (gridDim.x * blockDim.x) >> 5;
    float wid = g_w[(t * NRELC + (NRELC - 1)) * K32 + lane];
    float th = g_th[lane];
    float denom = fmaxf(g_sumraw[lane], 1e-7f);
    for (int e = warp; e < EE; e += nw) {
        float v = g_s[e * K32 + lane];
        float x = (v >= th) ? (v / denom) : 0.0f;
        g_x[e * K32 + lane] = x;
        g_s[e * K32 + lane] = wid * x;
        unsigned nz = __ballot_sync(0xFFFFFFFFu, x != 0.0f);
        if (lane == 0) g_actb[e] = nz ? 1 : 0;
    }
}

// ---------------- compact active triples into lists ----------------
__global__ void compact_kernel(const int* __restrict__ heads, const int* __restrict__ tails2) {
    int gtid = blockIdx.x * blockDim.x + threadIdx.x;
    if (gtid < K32) g_sumraw[gtid] = 0.0f;   // consumed by prior buildx; rewritten by sums
    int lane = threadIdx.x & 31;
    int stride = gridDim.x * blockDim.x;
    for (int i = gtid; i < NN; i += stride) {
        int h = heads[i], t2 = tails2[i];
        bool f = g_actb[h] != 0;
        bool b = g_actb[t2] != 0;
        unsigned mf = __ballot_sync(0xFFFFFFFFu, f);
        unsigned mb = __ballot_sync(0xFFFFFFFFu, b);
        unsigned lmask = (1u << lane) - 1u;
        if (mf) {
            int base;
            if (lane == 0) base = atomicAdd(&g_cnt[0], __popc(mf));
            base = __shfl_sync(0xFFFFFFFFu, base, 0);
            if (f) g_list_f[base + __popc(mf & lmask)] = i;
        }
        if (mb) {
            int base;
            if (lane == 0) base = atomicAdd(&g_cnt[1], __popc(mb));
            base = __shfl_sync(0xFFFFFFFFu, base, 0);
            if (b) g_list_b[base + __popc(mb & lmask)] = i;
        }
    }
}

// ---------------- propagate over compacted lists: warp per entry, 4-way unrolled ----------------
__global__ void prop_list_kernel(int t, const int* __restrict__ heads, const int* __restrict__ tails,
                                 const int* __restrict__ tails2, const int* __restrict__ rels) {
    int lane = threadIdx.x & 31;
    int warp = (blockIdx.x * blockDim.x + threadIdx.x) >> 5;
    int nw = (gridDim.x * blockDim.x) >> 5;
    const float* wt = &g_w[t * NRELC * K32];
    int cf = g_cnt[0], cb = g_cnt[1];

    for (int j0 = warp * 4; j0 < cf; j0 += nw * 4) {
        int n = min(4, cf - j0);
        int src[4], dst[4], rr[4];
        #pragma unroll
        for (int u = 0; u < 4; u++) if (u < n) {
            int i = g_list_f[j0 + u];
            src[u] = heads[i]; dst[u] = tails[i]; rr[u] = rels[i];
        }
        #pragma unroll
        for (int u = 0; u < 4; u++) if (u < n) {
            float mm = g_x[src[u] * K32 + lane] * wt[rr[u] * K32 + lane];
            if (mm != 0.0f) atomicAdd(&g_s[dst[u] * K32 + lane], mm);
        }
    }
    for (int j0 = warp * 4; j0 < cb; j0 += nw * 4) {
        int n = min(4, cb - j0);
        int src[4], dst[4], rr[4];
        #pragma unroll
        for (int u = 0; u < 4; u++) if (u < n) {
            int i = g_list_b[j0 + u];
            src[u] = tails2[i]; dst[u] = heads[i]; rr[u] = rels[i];
        }
        #pragma unroll
        for (int u = 0; u < 4; u++) if (u < n) {
            float mm = g_x[src[u] * K32 + lane] * wt[(rr[u] + RRR) * K32 + lane];
            if (mm != 0.0f) atomicAdd(&g_s[dst[u] * K32 + lane], mm);
        }
    }
}

// ---------------- per-(b,l) sums: single kernel with global atomics ----------------
__global__ void sums_kernel() {
    int tid = blockIdx.x * blockDim.x + threadIdx.x;
    int lane = threadIdx.x & 31;
    float a = 0.0f;
    int stride = gridDim.x * blockDim.x;
    for (int i = tid; i < EE * K32; i += stride) a += g_s[i];
    __shared__ float sm[8][32];
    sm[threadIdx.x >> 5][lane] = a;
    __syncthreads();
    if (threadIdx.x < 32) {
        float s = 0.0f;
        #pragma unroll
        for (int w = 0; w < 8; w++) s += sm[w][threadIdx.x];
        if (s != 0.0f) atomicAdd(&g_sumraw[threadIdx.x], s);
    }
}

// ---------------- final output ----------------
__global__ void out_kernel(float* __restrict__ out) {
    int stride = gridDim.x * blockDim.x;
    for (int idx = blockIdx.x * blockDim.x + threadIdx.x; idx < BBB * EE; idx += stride) {
        int b = idx / EE, e = idx - b * EE;
        float acc = 0.0f;
        #pragma unroll
        for (int l = 0; l < LL; l++) {
            int k = b * 3 + l;
            acc += g_s[e * K32 + k] / fmaxf(g_sumraw[k], 1e-7f);
        }
        out[idx] = acc;
    }
}

// ---------------- launch ----------------
extern "C" void kernel_launch(void* const* d_in, const int* in_sizes, int n_in,
                              void* d_out, int out_size) {
    const int*   input_x  = (const int*)d_in[0];
    const int*   input_r  = (const int*)d_in[1];
    const int*   e2triple = (const int*)d_in[2];
    const int*   triple2e = (const int*)d_in[3];
    const int*   r2triple = (const int*)d_in[4];
    const float* emb      = (const float*)d_in[5];
    const float* Wih_f    = (const float*)d_in[6];
    const float* Whh_f    = (const float*)d_in[7];
    const float* bih_f    = (const float*)d_in[8];
    const float* bhh_f    = (const float*)d_in[9];
    const float* Wih_b    = (const float*)d_in[10];
    const float* Whh_b    = (const float*)d_in[11];
    const float* bih_b    = (const float*)d_in[12];
    const float* bhh_b    = (const float*)d_in[13];
    const float* linW     = (const float*)d_in[14];
    const float* linb     = (const float*)d_in[15];

    const int* heads  = e2triple;
    const int* tails2 = e2triple + 2 * NN;
    const int* tails  = triple2e + NN;
    const int* rels   = r2triple;

    // LSTM part
    pre_kernel<<<dim3(128, 6), 256>>>(input_r, emb, Wih_f, bih_f, bhh_f, Wih_b, bih_b, bhh_b);
    for (int s = 0; s < 4; s++)
        step_kernel<<<dim3(128, 6), 256>>>(s, Whh_f, Whh_b);
    wlin_kernel<<<dim3(9, 8), 128>>>(linW, linb);

    // Hops
    for (int t = 0; t < TT; t++) {
        if (t == 0) {
            buildx0_kernel<<<256, 256>>>(input_x);
        } else {
            for (int p = 0; p < 4; p++) {
                sel_hist_kernel<<<128, 256>>>(p);
                sel_pick_kernel<<<24, 256>>>(p);
            }
            buildx_kernel<<<256, 256>>>(t);
        }
        compact_kernel<<<512, 256>>>(heads, tails2);
        prop_list_kernel<<<512, 256>>>(t, heads, tails, tails2, rels);
        sums_kernel<<<256, 256>>>();
    }

    out_kernel<<<512, 256>>>((float*)d_out);
}

// round 5
// speedup vs baseline: 3.5119x; 1.3124x over previous
#include <cuda_runtime.h>
#include <cstdint>

// ---------------- model constants ----------------
#define TT     3
#define LL     3
#define EE     50000
#define NN     1000000
#define RRR    200
#define NRELC  401
#define HHH    256
#define TOPKC  1000
#define BBB    8
#define K32    32
#define NB_LSTM 96

// ---------------- device scratch ----------------
__device__ float g_x[EE * K32];
__device__ float g_s[EE * K32];
__device__ unsigned char g_actb[EE];
__device__ float g_w[TT * NRELC * K32];
__device__ float g_h[6 * 4 * BBB * HHH];
__device__ float g_th[K32];
__device__ float g_sums[TT][K32];
__device__ int   g_cnt[1];
__device__ unsigned long long g_list[2 * NN];
__device__ unsigned g_hist8[24 * 256];
__device__ unsigned g_selb[24];
__device__ unsigned g_need[24];
__device__ int      g_ccnt[24];
__device__ unsigned g_cand[24 * EE];
__device__ unsigned g_barw = 0;

__device__ __forceinline__ float sigf(float x) { return 1.0f / (1.0f + expf(-x)); }
__device__ __forceinline__ float dot4(float4 a, float4 b) {
    return a.x * b.x + a.y * b.y + a.z * b.z + a.w * b.w;
}

// Replay-safe grid barrier: packed word = gen*256 + count. Each barrier adds
// exactly 256 total, so gen increments monotonically across graph replays.
__device__ __forceinline__ void grid_barrier() {
    __syncthreads();
    if (threadIdx.x == 0) {
        __threadfence();
        unsigned old = atomicAdd(&g_barw, 1u);
        unsigned gen = old >> 8;
        if ((old & 255u) == NB_LSTM - 1) {
            atomicAdd(&g_barw, 256u - NB_LSTM);
        } else {
            while (((*(volatile unsigned*)&g_barw) >> 8) == gen) __nanosleep(64);
        }
        __threadfence();
    }
    __syncthreads();
}

// ---------------- fused LSTM: pre-projection + 4 recurrent steps ----------------
// 96 blocks: blk = ld*16 + cg. Block owns kcols [cg*16, cg*16+16) of all 4 gates.
__global__ __launch_bounds__(256, 1) void lstm_fused_kernel(
    const int* __restrict__ input_r, const float* __restrict__ emb,
    const float* __restrict__ Wih_f, const float* __restrict__ bih_f, const float* __restrict__ bhh_f,
    const float* __restrict__ Wih_b, const float* __restrict__ bih_b, const float* __restrict__ bhh_b,
    const float* __restrict__ Whh_f, const float* __restrict__ Whh_b)
{
    int blk = blockIdx.x;
    int ld = blk >> 4, cg = blk & 15;
    int l = ld >> 1, dir = ld & 1;
    const float* Wih = (dir ? Wih_b : Wih_f) + l * 1024 * HHH;
    const float* Whh = (dir ? Whh_b : Whh_f) + l * 1024 * HHH;
    const float* bih = (dir ? bih_b : bih_f) + l * 1024;
    const float* bhh = (dir ? bhh_b : bhh_f) + l * 1024;

    __shared__ float sv[9][HHH];
    __shared__ float pre_s[4][8][64];
    __shared__ float sh[8][HHH];
    __shared__ float sc[8][16];
    __shared__ float sacc[4][16][8];
    __shared__ int sr[8];

    int tid = threadIdx.x, lane = tid & 31, warp = tid >> 5;
    int gate = warp & 3, kc8 = (warp >> 2) * 8;

    // housekeeping by block 0 (consumed only by later kernels)
    if (blk == 0) {
        for (int i = tid; i < TT * NRELC * K32; i += 256) g_w[i] = 0.0f;
        if (tid < TT * K32) ((float*)g_sums)[tid] = 0.0f;
        if (tid < K32) g_th[tid] = __uint_as_float(0x7F800000u);   // +inf
        for (int i = tid; i < 24 * 256; i += 256) g_hist8[i] = 0u;
    }

    if (tid < 8) sr[tid] = input_r[tid];
    __syncthreads();
    for (int i = tid; i < 9 * HHH; i += 256) {
        int v = i >> 8, c = i & 255;
        int rs = (v < 8) ? sr[v] : (NRELC - 1);
        sv[v][c] = emb[rs * HHH + c];
    }
    __syncthreads();

    float4 w[16];
    // ---- phase 0: input projections into pre_s ----
    #pragma unroll
    for (int r = 0; r < 8; r++) {
        int j = gate * 256 + cg * 16 + kc8 + r;
        const float4* w4 = (const float4*)(Wih + j * HHH);
        w[2 * r] = w4[lane * 2]; w[2 * r + 1] = w4[lane * 2 + 1];
    }
    #pragma unroll
    for (int r = 0; r < 8; r++) {
        int j = gate * 256 + cg * 16 + kc8 + r;
        float acc[9];
        #pragma unroll
        for (int v = 0; v < 9; v++) {
            const float4* s4 = (const float4*)sv[v];
            acc[v] = dot4(w[2 * r], s4[lane * 2]) + dot4(w[2 * r + 1], s4[lane * 2 + 1]);
        }
        #pragma unroll
        for (int v = 0; v < 9; v++)
            #pragma unroll
            for (int o = 16; o; o >>= 1) acc[v] += __shfl_down_sync(0xFFFFFFFFu, acc[v], o);
        if (lane == 0) {
            float bb = bih[j] + bhh[j];
            int row = gate * 16 + kc8 + r;
            #pragma unroll
            for (int t = 0; t < 4; t++)
                #pragma unroll
                for (int b = 0; b < 8; b++) {
                    int v = dir ? ((t == 0) ? 8 : b) : ((t < 3) ? b : 8);
                    pre_s[t][b][row] = acc[v] + bb;
                }
        }
    }
    // load Whh rows into regs (kept across all 4 steps)
    #pragma unroll
    for (int r = 0; r < 8; r++) {
        int j = gate * 256 + cg * 16 + kc8 + r;
        const float4* w4 = (const float4*)(Whh + j * HHH);
        w[2 * r] = w4[lane * 2]; w[2 * r + 1] = w4[lane * 2 + 1];
    }
    __syncthreads();

    // ---- 4 recurrent steps with grid barriers between ----
    for (int t = 0; t < 4; t++) {
        if (t > 0) {
            const float* hp = &g_h[((ld * 4 + (t - 1)) * 8) * HHH];
            for (int i = tid; i < 8 * HHH; i += 256) ((float*)sh)[i] = hp[i];
            __syncthreads();
        }
        #pragma unroll
        for (int r = 0; r < 8; r++) {
            float acc[8];
            #pragma unroll
            for (int b = 0; b < 8; b++) {
                if (t > 0) {
                    const float4* h4 = (const float4*)sh[b];
                    acc[b] = dot4(w[2 * r], h4[lane * 2]) + dot4(w[2 * r + 1], h4[lane * 2 + 1]);
                } else acc[b] = 0.0f;
            }
            #pragma unroll
            for (int b = 0; b < 8; b++)
                #pragma unroll
                for (int o = 16; o; o >>= 1) acc[b] += __shfl_down_sync(0xFFFFFFFFu, acc[b], o);
            if (lane == 0) {
                int kc = kc8 + r;
                #pragma unroll
                for (int b = 0; b < 8; b++)
                    sacc[gate][kc][b] = acc[b] + pre_s[t][b][gate * 16 + kc];
            }
        }
        __syncthreads();
        if (tid < 128) {
            int kc = tid >> 3, b = tid & 7;
            float gi = sacc[0][kc][b], gf = sacc[1][kc][b];
            float gg = sacc[2][kc][b], go = sacc[3][kc][b];
            float cp = (t > 0) ? sc[b][kc] : 0.0f;
            float c = sigf(gf) * cp + sigf(gi) * tanhf(gg);
            float h = sigf(go) * tanhf(c);
            sc[b][kc] = c;
            g_h[((ld * 4 + t) * 8 + b) * HHH + cg * 16 + kc] = h;
        }
        if (t < 3) grid_barrier();
    }
}

// ---------------- linear + softmax -> relation weights ----------------
__global__ void wlin_kernel(const float* __restrict__ linW, const float* __restrict__ linb) {
    int t = blockIdx.x / 3, l = blockIdx.x % 3, b = blockIdx.y;
    __shared__ float rnn[2 * HHH];
    __shared__ float logit[NRELC];
    __shared__ float red[128];
    int tid = threadIdx.x;

    const float* hf = &g_h[(((l * 2 + 0) * 4 + t) * BBB + b) * HHH];
    const float* hb = &g_h[(((l * 2 + 1) * 4 + (3 - t)) * BBB + b) * HHH];
    for (int i = tid; i < HHH; i += 128) { rnn[i] = hf[i]; rnn[HHH + i] = hb[i]; }
    __syncthreads();

    const float4* r4 = (const float4*)rnn;
    for (int n = tid; n < NRELC; n += 128) {
        const float4* w4 = (const float4*)(linW + n * 2 * HHH);
        float acc = 0.0f;
        for (int kk = 0; kk < (2 * HHH) / 4; kk++) acc += dot4(w4[kk], r4[kk]);
        logit[n] = acc + linb[n];
    }
    __syncthreads();

    float m = -1e30f;
    for (int n = tid; n < NRELC; n += 128) m = fmaxf(m, logit[n]);
    red[tid] = m; __syncthreads();
    for (int o = 64; o; o >>= 1) { if (tid < o) red[tid] = fmaxf(red[tid], red[tid + o]); __syncthreads(); }
    m = red[0]; __syncthreads();

    float s = 0.0f;
    for (int n = tid; n < NRELC; n += 128) {
        float e = expf((logit[n] - m) / 10.0f);
        logit[n] = e; s += e;
    }
    red[tid] = s; __syncthreads();
    for (int o = 64; o; o >>= 1) { if (tid < o) red[tid] += red[tid + o]; __syncthreads(); }
    s = red[0];

    int k = b * 3 + l;
    for (int n = tid; n < NRELC; n += 128)
        g_w[(t * NRELC + n) * K32 + k] = logit[n] / s;
}

// ---------------- select pass A: 8-bit histogram, coalesced float4 reads ----------------
__global__ void sel_histA_kernel() {
    __shared__ unsigned hist[24][257];
    int tid = threadIdx.x;
    for (int i = tid; i < 24 * 257; i += 256) ((unsigned*)hist)[i] = 0u;
    __syncthreads();

    int q = tid & 7, eo = tid >> 3;
    int base = blockIdx.x * 391;
    int lim = min(base + 391, EE);
    if (q < 6) {
        for (int e = base + eo; e < lim; e += 32) {
            float4 v = *(const float4*)&g_s[e * K32 + q * 4];
            #pragma unroll
            for (int c = 0; c < 4; c++) {
                unsigned u = __float_as_uint(c == 0 ? v.x : c == 1 ? v.y : c == 2 ? v.z : v.w);
                if (u == 0x80000000u) u = 0;
                atomicAdd(&hist[q * 4 + c][u >> 24], 1u);
            }
        }
    }
    __syncthreads();
    for (int i = tid; i < 24 * 256; i += 256) {
        unsigned v = hist[i >> 8][i & 255];
        if (v) atomicAdd(&g_hist8[i], v);
    }
}

__global__ void sel_pickA_kernel() {
    int k = blockIdx.x, tid = threadIdx.x;
    __shared__ unsigned h[256], scan[256];
    unsigned v = g_hist8[k * 256 + tid];
    h[tid] = v; scan[tid] = v;
    __syncthreads();
    for (int o = 1; o < 256; o <<= 1) {
        unsigned add = (tid + o < 256) ? scan[tid + o] : 0u;
        __syncthreads();
        scan[tid] += add;
        __syncthreads();
    }
    unsigned need = TOPKC;
    unsigned cumIncl = scan[tid];
    unsigned cumAbove = cumIncl - h[tid];
    if (cumIncl >= need && cumAbove < need) {
        g_need[k] = need - cumAbove;
        g_selb[k] = (unsigned)tid;
    }
    g_hist8[k * 256 + tid] = 0u;
    if (tid == 0) g_ccnt[k] = 0;
}

// ---------------- candidate compaction (matching top byte, nonzero only) ----------------
__global__ void cand_compact_kernel() {
    __shared__ int scnt[24], sbase[24], sidx[24];
    __shared__ unsigned ssel[24];
    int tid = threadIdx.x;
    if (tid < 24) { scnt[tid] = 0; ssel[tid] = g_selb[tid]; }
    __syncthreads();

    int q = tid & 7, eo = tid >> 3;
    int base = blockIdx.x * 391;
    int lim = min(base + 391, EE);
    if (q < 6) {
        for (int e = base + eo; e < lim; e += 32) {
            float4 v = *(const float4*)&g_s[e * K32 + q * 4];
            #pragma unroll
            for (int c = 0; c < 4; c++) {
                unsigned u = __float_as_uint(c == 0 ? v.x : c == 1 ? v.y : c == 2 ? v.z : v.w);
                if (u == 0x80000000u) u = 0;
                if (u != 0 && (u >> 24) == ssel[q * 4 + c]) atomicAdd(&scnt[q * 4 + c], 1);
            }
        }
    }
    __syncthreads();
    if (tid < 24) { sbase[tid] = atomicAdd(&g_ccnt[tid], scnt[tid]); sidx[tid] = 0; }
    __syncthreads();
    if (q < 6) {
        for (int e = base + eo; e < lim; e += 32) {
            float4 v = *(const float4*)&g_s[e * K32 + q * 4];
            #pragma unroll
            for (int c = 0; c < 4; c++) {
                unsigned u = __float_as_uint(c == 0 ? v.x : c == 1 ? v.y : c == 2 ? v.z : v.w);
                if (u == 0x80000000u) u = 0;
                int k = q * 4 + c;
                if (u != 0 && (u >> 24) == ssel[k]) {
                    int off = atomicAdd(&sidx[k], 1);
                    g_cand[k * EE + sbase[k] + off] = u;
                }
            }
        }
    }
}

// ---------------- finish selection on remaining 24 bits ----------------
__global__ void cand_select_kernel() {
    int k = blockIdx.x, tid = threadIdx.x;
    int cnt = g_ccnt[k];
    unsigned need = g_need[k];
    unsigned selb = g_selb[k];
    __shared__ unsigned h[256], scan[256];
    __shared__ unsigned s_pref, s_need;

    if ((unsigned)cnt < need) {   // threshold falls among zeros (selb must be 0)
        if (tid == 0) g_th[k] = 0.0f;
        return;
    }
    unsigned pref = 0;
    for (int p = 2; p >= 0; p--) {
        h[tid] = 0u;
        __syncthreads();
        for (int i = tid; i < cnt; i += 256) {
            unsigned u = g_cand[k * EE + i] & 0xFFFFFFu;
            bool ok = (p == 2) || ((u >> (8 * p + 8)) == pref);
            if (ok) atomicAdd(&h[(u >> (8 * p)) & 255u], 1u);
        }
        __syncthreads();
        scan[tid] = h[tid];
        __syncthreads();
        for (int o = 1; o < 256; o <<= 1) {
            unsigned add = (tid + o < 256) ? scan[tid + o] : 0u;
            __syncthreads();
            scan[tid] += add;
            __syncthreads();
        }
        unsigned cumIncl = scan[tid];
        unsigned cumAbove = cumIncl - h[tid];
        if (cumIncl >= need && cumAbove < need) {
            s_pref = (pref << 8) | (unsigned)tid;
            s_need = need - cumAbove;
        }
        __syncthreads();
        pref = s_pref; need = s_need;
        __syncthreads();
    }
    if (tid == 0) g_th[k] = __uint_as_float((selb << 24) | pref);
}

// ---------------- x builders (fused identity-init + activity + sums) ----------------
__global__ void buildx0_kernel(const int* __restrict__ input_x) {
    __shared__ int xs[BBB];
    __shared__ float sm[8][32];
    if (threadIdx.x < BBB) xs[threadIdx.x] = input_x[threadIdx.x];
    __syncthreads();
    int gtid = blockIdx.x * blockDim.x + threadIdx.x;
    if (gtid == 0) g_cnt[0] = 0;
    int lane = threadIdx.x & 31;
    int warp = gtid >> 5;
    int nw = (gridDim.x * blockDim.x) >> 5;
    float wid = g_w[(0 * NRELC + (NRELC - 1)) * K32 + lane];
    int bsel = (lane < 24) ? (lane / 3) : 0;
    float sacc = 0.0f;
    for (int e = warp; e < EE; e += nw) {
        float x = (lane < 24 && xs[bsel] == e) ? 1.0f : 0.0f;
        g_x[e * K32 + lane] = x;
        float s = wid * x;
        g_s[e * K32 + lane] = s;
        sacc += s;
        unsigned nz = __ballot_sync(0xFFFFFFFFu, x != 0.0f);
        if (lane == 0) g_actb[e] = nz ? 1 : 0;
    }
    sm[threadIdx.x >> 5][lane] = sacc;
    __syncthreads();
    if (threadIdx.x < 32) {
        float s = 0.0f;
        #pragma unroll
        for (int w = 0; w < 8; w++) s += sm[w][threadIdx.x];
        if (s != 0.0f) atomicAdd(&g_sums[0][threadIdx.x], s);
    }
}

__global__ void buildx_kernel(int t) {
    __shared__ float sm[8][32];
    int gtid = blockIdx.x * blockDim.x + threadIdx.x;
    if (gtid == 0) g_cnt[0] = 0;
    int lane = threadIdx.x & 31;
    int warp = gtid >> 5;
    int nw = (gridDim.x * blockDim.x) >> 5;
    float wid = g_w[(t * NRELC + (NRELC - 1)) * K32 + lane];
    float th = g_th[lane];
    float denom = fmaxf(g_sums[t - 1][lane], 1e-7f);
    float sacc = 0.0f;
    for (int e = warp; e < EE; e += nw) {
        float v = g_s[e * K32 + lane];
        float x = (v >= th) ? (v / denom) : 0.0f;
        g_x[e * K32 + lane] = x;
        float s = wid * x;
        g_s[e * K32 + lane] = s;
        sacc += s;
        unsigned nz = __ballot_sync(0xFFFFFFFFu, x != 0.0f);
        if (lane == 0) g_actb[e] = nz ? 1 : 0;
    }
    sm[threadIdx.x >> 5][lane] = sacc;
    __syncthreads();
    if (threadIdx.x < 32) {
        float s = 0.0f;
        #pragma unroll
        for (int w = 0; w < 8; w++) s += sm[w][threadIdx.x];
        if (s != 0.0f) atomicAdd(&g_sums[t][threadIdx.x], s);
    }
}

// ---------------- compact active triples into a single packed list ----------------
__global__ void compact_kernel(const int* __restrict__ heads, const int* __restrict__ tails,
                               const int* __restrict__ tails2, const int* __restrict__ rels) {
    int gtid = blockIdx.x * blockDim.x + threadIdx.x;
    int lane = threadIdx.x & 31;
    unsigned lmask = (1u << lane) - 1u;
    int stride = gridDim.x * blockDim.x;
    for (int i = gtid; i < NN; i += stride) {
        int h = heads[i], t2 = tails2[i];
        bool f = g_actb[h] != 0;
        bool bk = g_actb[t2] != 0;
        unsigned mf = __ballot_sync(0xFFFFFFFFu, f);
        unsigned mb = __ballot_sync(0xFFFFFFFFu, bk);
        if (mf) {
            int base;
            if (lane == 0) base = atomicAdd(&g_cnt[0], __popc(mf));
            base = __shfl_sync(0xFFFFFFFFu, base, 0);
            if (f) {
                unsigned r = (unsigned)rels[i];
                unsigned tl = (unsigned)tails[i];
                unsigned long long pk = ((unsigned long long)r << 32) | (tl << 16) | (unsigned)h;
                g_list[base + __popc(mf & lmask)] = pk;
            }
        }
        if (mb) {
            int base;
            if (lane == 0) base = atomicAdd(&g_cnt[0], __popc(mb));
            base = __shfl_sync(0xFFFFFFFFu, base, 0);
            if (bk) {
                unsigned r = (unsigned)rels[i] + RRR;
                unsigned long long pk = ((unsigned long long)r << 32) | ((unsigned)h << 16) | (unsigned)t2;
                g_list[base + __popc(mb & lmask)] = pk;
            }
        }
    }
}

// ---------------- propagate over packed list + accumulate sums ----------------
__global__ void prop_kernel(int t) {
    __shared__ float sm[8][32];
    int lane = threadIdx.x & 31;
    int warp = (blockIdx.x * blockDim.x + threadIdx.x) >> 5;
    int nw = (gridDim.x * blockDim.x) >> 5;
    const float* wt = &g_w[t * NRELC * K32];
    int cnt = g_cnt[0];
    float sacc = 0.0f;

    for (int j0 = warp * 6; j0 < cnt; j0 += nw * 6) {
        int n = min(6, cnt - j0);
        unsigned long long e[6];
        #pragma unroll
        for (int u = 0; u < 6; u++) if (u < n) e[u] = g_list[j0 + u];
        float xv[6], wv[6];
        #pragma unroll
        for (int u = 0; u < 6; u++) if (u < n) {
            int src = (int)(e[u] & 0xFFFFu);
            int rel = (int)(e[u] >> 32);
            xv[u] = g_x[src * K32 + lane];
            wv[u] = wt[rel * K32 + lane];
        }
        #pragma unroll
        for (int u = 0; u < 6; u++) if (u < n) {
            int dst = (int)((e[u] >> 16) & 0xFFFFu);
            float mm = xv[u] * wv[u];
            sacc += mm;
            if (mm != 0.0f) atomicAdd(&g_s[dst * K32 + lane], mm);
        }
    }
    sm[threadIdx.x >> 5][lane] = sacc;
    __syncthreads();
    if (threadIdx.x < 32) {
        float s = 0.0f;
        #pragma unroll
        for (int w = 0; w < 8; w++) s += sm[w][threadIdx.x];
        if (s != 0.0f) atomicAdd(&g_sums[t][threadIdx.x], s);
    }
}

// ---------------- final output ----------------
__global__ void out_kernel(float* __restrict__ out) {
    int stride = gridDim.x * blockDim.x;
    for (int idx = blockIdx.x * blockDim.x + threadIdx.x; idx < BBB * EE; idx += stride) {
        int b = idx / EE, e = idx - b * EE;
        float acc = 0.0f;
        #pragma unroll
        for (int l = 0; l < LL; l++) {
            int k = b * 3 + l;
            acc += g_s[e * K32 + k] / fmaxf(g_sums[TT - 1][k], 1e-7f);
        }
        out[idx] = acc;
    }
}

// ---------------- launch ----------------
extern "C" void kernel_launch(void* const* d_in, const int* in_sizes, int n_in,
                              void* d_out, int out_size) {
    const int*   input_x  = (const int*)d_in[0];
    const int*   input_r  = (const int*)d_in[1];
    const int*   e2triple = (const int*)d_in[2];
    const int*   triple2e = (const int*)d_in[3];
    const int*   r2triple = (const int*)d_in[4];
    const float* emb      = (const float*)d_in[5];
    const float* Wih_f    = (const float*)d_in[6];
    const float* Whh_f    = (const float*)d_in[7];
    const float* bih_f    = (const float*)d_in[8];
    const float* bhh_f    = (const float*)d_in[9];
    const float* Wih_b    = (const float*)d_in[10];
    const float* Whh_b    = (const float*)d_in[11];
    const float* bih_b    = (const float*)d_in[12];
    const float* bhh_b    = (const float*)d_in[13];
    const float* linW     = (const float*)d_in[14];
    const float* linb     = (const float*)d_in[15];

    const int* heads  = e2triple;
    const int* tails2 = e2triple + 2 * NN;
    const int* tails  = triple2e + NN;
    const int* rels   = r2triple;

    lstm_fused_kernel<<<NB_LSTM, 256>>>(input_r, emb, Wih_f, bih_f, bhh_f,
                                        Wih_b, bih_b, bhh_b, Whh_f, Whh_b);
    wlin_kernel<<<dim3(9, 8), 128>>>(linW, linb);

    for (int t = 0; t < TT; t++) {
        if (t == 0) {
            buildx0_kernel<<<256, 256>>>(input_x);
        } else {
            sel_histA_kernel<<<128, 256>>>();
            sel_pickA_kernel<<<24, 256>>>();
            cand_compact_kernel<<<128, 256>>>();
            cand_select_kernel<<<24, 256>>>();
            buildx_kernel<<<256, 256>>>(t);
        }
        compact_kernel<<<512, 256>>>(heads, tails, tails2, rels);
        prop_kernel<<<512, 256>>>(t);
    }

    out_kernel<<<512, 256>>>((float*)d_out);
}